// round 1
// baseline (speedup 1.0000x reference)
#include <cuda_runtime.h>

#define BS    64
#define SL    8192
#define EDIM  64
#define DDIM  64
#define VOCAB 1088
#define NVAL  64
#define SPLIT 4
#define CHUNK (SL / SPLIT)

// Scratch (no allocations allowed in kernel_launch)
__device__ float g_SK[BS * VOCAB];
__device__ float g_SV[BS * NVAL];
__device__ float g_Pm[BS * SPLIT];
__device__ float g_Pz[BS * SPLIT];
__device__ float g_Pb[BS * SPLIT * NVAL];
__device__ int   g_cnt[BS];   // zero-initialized; reset by combining block each launch

// ---------------------------------------------------------------------------
// Kernel A: build per-batch score tables.
//   Q[b,d]  = embK[q[b]] . Wq_w[d,:] + Wq_b[d]
//   Qk[b,e] = sum_d Wk_w[d,64+e] * Q[b,d] * 0.125
//   SV[b,n] = sum_d Wk_w[d,n]    * Q[b,d] * 0.125
//   SK[b,v] = embK[v] . Qk[b]
// grid = 17 vocab-tiles (64 rows) x 4 batch-tiles (16 batches), 256 threads.
// ---------------------------------------------------------------------------
__global__ __launch_bounds__(256) void tables_kernel(
    const int*   __restrict__ q,
    const float* __restrict__ embK,
    const float* __restrict__ Wk_w,   // (64, 128) row-major
    const float* __restrict__ Wq_w,   // (64, 64) row-major
    const float* __restrict__ Wq_b)
{
    const int bt = blockIdx.x & 3;      // batch tile (16 batches)
    const int vt = blockIdx.x >> 2;     // vocab tile (64 rows)
    const int b0 = bt * 16;
    const int v0 = vt * 64;
    const int tid = threadIdx.x;

    __shared__ float Qs [16 * 64];
    __shared__ float Qks[16 * 64];
    __shared__ float Es [64 * 65];      // padded: conflict-free column reads

    // Phase 1: Q for this block's 16 batches (redundant across vt tiles; tiny)
    for (int idx = tid; idx < 1024; idx += 256) {
        const int bl = idx >> 6, d = idx & 63;
        const int qi = q[b0 + bl];
        const float* er = embK + (size_t)qi * EDIM;
        const float* wr = Wq_w + (size_t)d  * EDIM;
        float acc = Wq_b[d];
        #pragma unroll
        for (int e = 0; e < EDIM; e++) acc = fmaf(er[e], wr[e], acc);
        Qs[idx] = acc;
    }
    // Load this block's embK tile (coalesced) into padded shared
    for (int i = tid; i < 64 * 64; i += 256) {
        Es[(i >> 6) * 65 + (i & 63)] = embK[(size_t)v0 * EDIM + i];
    }
    __syncthreads();

    // Phase 2: Qk (and SV, once, by the vt==0 tiles)
    for (int idx = tid; idx < 1024; idx += 256) {
        const int bl = idx >> 6, e = idx & 63;
        float acc = 0.f;
        #pragma unroll
        for (int d = 0; d < DDIM; d++)
            acc = fmaf(Wk_w[d * 128 + 64 + e], Qs[bl * 64 + d], acc);
        Qks[idx] = acc * 0.125f;
    }
    if (vt == 0) {
        for (int idx = tid; idx < 1024; idx += 256) {
            const int bl = idx >> 6, n = idx & 63;
            float acc = 0.f;
            #pragma unroll
            for (int d = 0; d < DDIM; d++)
                acc = fmaf(Wk_w[d * 128 + n], Qs[bl * 64 + d], acc);
            g_SV[(b0 + bl) * NVAL + n] = acc * 0.125f;
        }
    }
    __syncthreads();

    // Phase 3: SK tile = Es(64x64) x Qks(16x64)^T ; coalesced writes
    for (int idx = tid; idx < 1024; idx += 256) {
        const int bl = idx >> 6, vl = idx & 63;
        float acc = 0.f;
        #pragma unroll
        for (int e = 0; e < EDIM; e++)
            acc = fmaf(Es[vl * 65 + e], Qks[bl * 64 + e], acc);
        g_SK[(size_t)(b0 + bl) * VOCAB + v0 + vl] = acc;
    }
}

// ---------------------------------------------------------------------------
// Kernel B: streaming softmax-histogram.
// grid = 64 batches x 4 splits, 256 threads, 8 elements/thread.
// The last block per batch combines the 4 partial softmaxes (threadfence +
// atomic counter; counter self-resets so the kernel is graph-replayable).
// ---------------------------------------------------------------------------
__global__ __launch_bounds__(256) void attn_kernel(
    const int* __restrict__ x,
    float*     __restrict__ out)
{
    const int b    = blockIdx.x >> 2;
    const int sp   = blockIdx.x & 3;
    const int tid  = threadIdx.x;
    const int warp = tid >> 5;
    const int lane = tid & 31;

    __shared__ float SKs[VOCAB];
    __shared__ float SVs[NVAL];
    __shared__ float bins[8][NVAL];     // warp-replicated histograms
    __shared__ float red[8];
    __shared__ int   lastFlag;

    for (int i = tid; i < VOCAB; i += 256) SKs[i] = g_SK[(size_t)b * VOCAB + i];
    if (tid < NVAL) SVs[tid] = g_SV[b * NVAL + tid];
    for (int i = tid; i < 8 * NVAL; i += 256) (&bins[0][0])[i] = 0.f;
    __syncthreads();

    const int* kp = x + (size_t)b * 2 * SL + sp * CHUNK;
    const int* vp = kp + SL;
    const int4 k0 = reinterpret_cast<const int4*>(kp)[tid];
    const int4 k1 = reinterpret_cast<const int4*>(kp)[tid + 256];
    const int4 w0 = reinterpret_cast<const int4*>(vp)[tid];
    const int4 w1 = reinterpret_cast<const int4*>(vp)[tid + 256];

    const int kk[8] = {k0.x, k0.y, k0.z, k0.w, k1.x, k1.y, k1.z, k1.w};
    const int vv[8] = {w0.x - NVAL, w0.y - NVAL, w0.z - NVAL, w0.w - NVAL,
                       w1.x - NVAL, w1.y - NVAL, w1.z - NVAL, w1.w - NVAL};

    float s[8];
    float m = -1e30f;
    #pragma unroll
    for (int i = 0; i < 8; i++) {
        s[i] = SKs[kk[i]] + SVs[vv[i]];
        m = fmaxf(m, s[i]);
    }
    #pragma unroll
    for (int o = 16; o > 0; o >>= 1) m = fmaxf(m, __shfl_xor_sync(0xffffffffu, m, o));
    if (lane == 0) red[warp] = m;
    __syncthreads();
    float bm = red[0];
    #pragma unroll
    for (int w = 1; w < 8; w++) bm = fmaxf(bm, red[w]);

    float z = 0.f;
    #pragma unroll
    for (int i = 0; i < 8; i++) {
        const float e = __expf(s[i] - bm);
        z += e;
        atomicAdd(&bins[warp][vv[i]], e);
    }
    #pragma unroll
    for (int o = 16; o > 0; o >>= 1) z += __shfl_xor_sync(0xffffffffu, z, o);
    __syncthreads();                    // red free to reuse; shared atomics done
    if (lane == 0) red[warp] = z;
    __syncthreads();

    if (tid < NVAL) {
        float bsum = 0.f;
        #pragma unroll
        for (int w = 0; w < 8; w++) bsum += bins[w][tid];
        g_Pb[(b * SPLIT + sp) * NVAL + tid] = bsum;
    }
    if (tid == 0) {
        float Z = 0.f;
        #pragma unroll
        for (int w = 0; w < 8; w++) Z += red[w];
        g_Pm[b * SPLIT + sp] = bm;
        g_Pz[b * SPLIT + sp] = Z;
    }
    __syncthreads();

    if (tid == 0) {
        __threadfence();                            // publish partials (release)
        const int old = atomicAdd(&g_cnt[b], 1);
        lastFlag = (old == SPLIT - 1) ? 1 : 0;
        __threadfence();                            // acquire for the reads below
    }
    __syncthreads();

    if (lastFlag) {
        if (tid < NVAL) {
            volatile float* vPm = g_Pm + b * SPLIT;
            volatile float* vPz = g_Pz + b * SPLIT;
            volatile float* vPb = g_Pb + (size_t)b * SPLIT * NVAL;
            float M = vPm[0];
            #pragma unroll
            for (int s2 = 1; s2 < SPLIT; s2++) M = fmaxf(M, vPm[s2]);
            float Zt = 0.f, num = 0.f;
            #pragma unroll
            for (int s2 = 0; s2 < SPLIT; s2++) {
                const float w = __expf(vPm[s2] - M);
                Zt  += vPz[s2] * w;
                num += vPb[s2 * NVAL + tid] * w;
            }
            out[b * NVAL + tid] = num / Zt;
        }
        __syncthreads();
        if (tid == 0) g_cnt[b] = 0;                 // re-arm for next replay
    }
}

// ---------------------------------------------------------------------------
// Inputs (metadata order): x(int32), q(int32), embK, Wk_w, Wk_b, Wq_w, Wq_b.
// Wk_b is softmax-invariant (constant per batch) and intentionally unused.
// ---------------------------------------------------------------------------
extern "C" void kernel_launch(void* const* d_in, const int* in_sizes, int n_in,
                              void* d_out, int out_size)
{
    const int*   x    = (const int*)  d_in[0];
    const int*   q    = (const int*)  d_in[1];
    const float* embK = (const float*)d_in[2];
    const float* Wk_w = (const float*)d_in[3];
    const float* Wq_w = (const float*)d_in[5];
    const float* Wq_b = (const float*)d_in[6];
    float* out = (float*)d_out;

    tables_kernel<<<68, 256>>>(q, embK, Wk_w, Wq_w, Wq_b);
    attn_kernel<<<BS * SPLIT, 256>>>(x, out);
}

// round 2
// speedup vs baseline: 1.3588x; 1.3588x over previous
#include <cuda_runtime.h>

#define BS    64
#define SL    8192
#define EDIM  64
#define DDIM  64
#define VOCAB 1088
#define NVAL  64
#define SPLIT 8
#define CHUNK (SL / SPLIT)          // 1024
#define EPT   (CHUNK / 256)         // 4 elements per thread

// Scratch (no allocations allowed in kernel_launch)
__device__ float g_SK[BS * VOCAB];
__device__ float g_SV[BS * NVAL];
__device__ float g_Pm[BS * SPLIT];
__device__ float g_Pz[BS * SPLIT];
__device__ float g_Pb[BS * SPLIT * NVAL];
__device__ int   g_cnt[BS];   // zero-init; reset by combining block each launch

// ---------------------------------------------------------------------------
// Kernel A: build per-batch score tables.
//   Q[b,d]  = embK[q[b]] . Wq_w[d,:] + Wq_b[d]
//   Qk[b,e] = sum_d Wk_w[d,64+e] * Q[b,d] * 0.125
//   SV[b,n] = sum_d Wk_w[d,n]    * Q[b,d] * 0.125
//   SK[b,v] = embK[v] . Qk[b]
// grid = 17 vocab-tiles (64 rows) x 4 batch-tiles (16 batches), 256 threads.
// All inner-loop operands staged in shared, coalesced, bank-conflict-free.
// ---------------------------------------------------------------------------
__global__ __launch_bounds__(256) void tables_kernel(
    const int*   __restrict__ q,
    const float* __restrict__ embK,
    const float* __restrict__ Wk_w,   // (64, 128) row-major
    const float* __restrict__ Wq_w,   // (64, 64) row-major
    const float* __restrict__ Wq_b)
{
    const int bt = blockIdx.x & 3;      // batch tile (16 batches)
    const int vt = blockIdx.x >> 2;     // vocab tile (64 rows)
    const int b0 = bt * 16;
    const int v0 = vt * 64;
    const int tid = threadIdx.x;

    __shared__ float Wqs[64 * 65];      // padded (stride 65): conflict-free row reads
    __shared__ float Eq [16 * 64];      // embK rows of the 16 queries
    __shared__ float Qs [16 * 64];
    __shared__ float Qks[16 * 64];
    __shared__ float Es [64 * 65];      // padded embK vocab tile
    __shared__ int   qsh[16];

    if (tid < 16) qsh[tid] = q[b0 + tid];
    // Coalesced load of Wq into padded shared
    for (int i = tid; i < 64 * 64; i += 256)
        Wqs[(i >> 6) * 65 + (i & 63)] = Wq_w[i];
    // Coalesced load of this block's embK vocab tile
    for (int i = tid; i < 64 * 64; i += 256)
        Es[(i >> 6) * 65 + (i & 63)] = embK[(size_t)v0 * EDIM + i];
    __syncthreads();

    // Coalesced load of the 16 query embedding rows
    for (int i = tid; i < 16 * 64; i += 256)
        Eq[i] = embK[(size_t)qsh[i >> 6] * EDIM + (i & 63)];
    __syncthreads();

    // Phase 1: Q (shared-only inner loop; Eq broadcast, Wqs conflict-free)
    for (int idx = tid; idx < 1024; idx += 256) {
        const int bl = idx >> 6, d = idx & 63;
        float acc = Wq_b[d];
        #pragma unroll
        for (int e = 0; e < EDIM; e++)
            acc = fmaf(Eq[bl * 64 + e], Wqs[d * 65 + e], acc);
        Qs[idx] = acc;
    }
    __syncthreads();

    // Phase 2: Qk (Wk_w reads are lane-coalesced: e contiguous) + SV once
    for (int idx = tid; idx < 1024; idx += 256) {
        const int bl = idx >> 6, e = idx & 63;
        float acc = 0.f;
        #pragma unroll
        for (int d = 0; d < DDIM; d++)
            acc = fmaf(Wk_w[d * 128 + 64 + e], Qs[bl * 64 + d], acc);
        Qks[idx] = acc * 0.125f;
    }
    if (vt == 0) {
        for (int idx = tid; idx < 1024; idx += 256) {
            const int bl = idx >> 6, n = idx & 63;
            float acc = 0.f;
            #pragma unroll
            for (int d = 0; d < DDIM; d++)
                acc = fmaf(Wk_w[d * 128 + n], Qs[bl * 64 + d], acc);
            g_SV[(b0 + bl) * NVAL + n] = acc * 0.125f;
        }
    }
    __syncthreads();

    // Phase 3: SK tile = Es(64x64) x Qks(16x64)^T ; coalesced writes
    for (int idx = tid; idx < 1024; idx += 256) {
        const int bl = idx >> 6, vl = idx & 63;
        float acc = 0.f;
        #pragma unroll
        for (int e = 0; e < EDIM; e++)
            acc = fmaf(Es[vl * 65 + e], Qks[bl * 64 + e], acc);
        g_SK[(size_t)(b0 + bl) * VOCAB + v0 + vl] = acc;
    }
}

// ---------------------------------------------------------------------------
// Kernel B: streaming softmax-histogram.
// grid = 64 batches x 8 splits (512 blocks), 256 threads, 4 elements/thread.
// Last block per batch combines the 8 partial softmaxes (fence + counter,
// self-resetting for graph replay).
// ---------------------------------------------------------------------------
__global__ __launch_bounds__(256) void attn_kernel(
    const int* __restrict__ x,
    float*     __restrict__ out)
{
    const int b    = blockIdx.x >> 3;
    const int sp   = blockIdx.x & 7;
    const int tid  = threadIdx.x;
    const int warp = tid >> 5;
    const int lane = tid & 31;

    __shared__ float SKs[VOCAB];
    __shared__ float SVs[NVAL];
    __shared__ float bins[8][NVAL];     // warp-replicated histograms
    __shared__ float red[8];
    __shared__ int   lastFlag;

    // Vectorized table loads
    {
        const float4* src = reinterpret_cast<const float4*>(g_SK + (size_t)b * VOCAB);
        float4* dst = reinterpret_cast<float4*>(SKs);
        for (int i = tid; i < VOCAB / 4; i += 256) dst[i] = src[i];
    }
    if (tid < NVAL) SVs[tid] = g_SV[b * NVAL + tid];
    for (int i = tid; i < 8 * NVAL; i += 256) (&bins[0][0])[i] = 0.f;
    __syncthreads();

    const int* kp = x + (size_t)b * 2 * SL + sp * CHUNK;
    const int* vp = kp + SL;
    const int4 k0 = reinterpret_cast<const int4*>(kp)[tid];
    const int4 w0 = reinterpret_cast<const int4*>(vp)[tid];

    const int kk[EPT] = {k0.x, k0.y, k0.z, k0.w};
    const int vv[EPT] = {w0.x - NVAL, w0.y - NVAL, w0.z - NVAL, w0.w - NVAL};

    float s[EPT];
    float m = -1e30f;
    #pragma unroll
    for (int i = 0; i < EPT; i++) {
        s[i] = SKs[kk[i]] + SVs[vv[i]];
        m = fmaxf(m, s[i]);
    }
    #pragma unroll
    for (int o = 16; o > 0; o >>= 1) m = fmaxf(m, __shfl_xor_sync(0xffffffffu, m, o));
    if (lane == 0) red[warp] = m;
    __syncthreads();
    float bm = red[0];
    #pragma unroll
    for (int w = 1; w < 8; w++) bm = fmaxf(bm, red[w]);

    float z = 0.f;
    #pragma unroll
    for (int i = 0; i < EPT; i++) {
        const float e = __expf(s[i] - bm);
        z += e;
        atomicAdd(&bins[warp][vv[i]], e);
    }
    #pragma unroll
    for (int o = 16; o > 0; o >>= 1) z += __shfl_xor_sync(0xffffffffu, z, o);
    __syncthreads();                    // shared atomics done; red reusable
    if (lane == 0) red[warp] = z;
    __syncthreads();

    if (tid < NVAL) {
        float bsum = 0.f;
        #pragma unroll
        for (int w = 0; w < 8; w++) bsum += bins[w][tid];
        g_Pb[(b * SPLIT + sp) * NVAL + tid] = bsum;
    }
    if (tid == 0) {
        float Z = 0.f;
        #pragma unroll
        for (int w = 0; w < 8; w++) Z += red[w];
        g_Pm[b * SPLIT + sp] = bm;
        g_Pz[b * SPLIT + sp] = Z;
    }
    __syncthreads();

    if (tid == 0) {
        __threadfence();                            // publish partials (release)
        const int old = atomicAdd(&g_cnt[b], 1);
        lastFlag = (old == SPLIT - 1) ? 1 : 0;
        __threadfence();                            // acquire for the reads below
    }
    __syncthreads();

    if (lastFlag) {
        if (tid < NVAL) {
            volatile float* vPm = g_Pm + b * SPLIT;
            volatile float* vPz = g_Pz + b * SPLIT;
            volatile float* vPb = g_Pb + (size_t)b * SPLIT * NVAL;
            float M = vPm[0];
            #pragma unroll
            for (int s2 = 1; s2 < SPLIT; s2++) M = fmaxf(M, vPm[s2]);
            float Zt = 0.f, num = 0.f;
            #pragma unroll
            for (int s2 = 0; s2 < SPLIT; s2++) {
                const float w = __expf(vPm[s2] - M);
                Zt  += vPz[s2] * w;
                num += vPb[s2 * NVAL + tid] * w;
            }
            out[b * NVAL + tid] = num / Zt;
        }
        __syncthreads();
        if (tid == 0) g_cnt[b] = 0;                 // re-arm for next replay
    }
}

// ---------------------------------------------------------------------------
// Inputs (metadata order): x(int32), q(int32), embK, Wk_w, Wk_b, Wq_w, Wq_b.
// Wk_b is softmax-invariant (constant per batch) and intentionally unused.
// ---------------------------------------------------------------------------
extern "C" void kernel_launch(void* const* d_in, const int* in_sizes, int n_in,
                              void* d_out, int out_size)
{
    const int*   x    = (const int*)  d_in[0];
    const int*   q    = (const int*)  d_in[1];
    const float* embK = (const float*)d_in[2];
    const float* Wk_w = (const float*)d_in[3];
    const float* Wq_w = (const float*)d_in[5];
    const float* Wq_b = (const float*)d_in[6];
    float* out = (float*)d_out;

    tables_kernel<<<68, 256>>>(q, embK, Wk_w, Wq_w, Wq_b);
    attn_kernel<<<BS * SPLIT, 256>>>(x, out);
}